// round 15
// baseline (speedup 1.0000x reference)
#include <cuda_runtime.h>
#include <cstdint>

// Problem constants (from reference)
#define SIGMA_INV 1.0e4f   // 1/SIGMA
#define GAMMA_INV 1.0e4f   // 1/GAMMA
#define ZFARV 100.0f
#define ZNEARV 1.0f
#define EPSV 1e-10f
#define MAX_F 100000
#define Q14_SCALE 8191.0f
#define Q14_INV   (1.0f / 8191.0f)

__device__ uint4 g_facen[MAX_F];

__device__ __forceinline__ unsigned long long q14(float a) {
    int ia = __float2int_rn(a * Q14_SCALE);
    return (unsigned long long)((unsigned)ia & 0x3FFFu);
}

__global__ void gather_face_normals_kernel(const int* __restrict__ faces,
                                           const float* __restrict__ vn,
                                           int F) {
    int f = blockIdx.x * blockDim.x + threadIdx.x;
    if (f < F) {
        int v0 = __ldg(&faces[3 * f + 0]);
        int v1 = __ldg(&faces[3 * f + 1]);
        int v2 = __ldg(&faces[3 * f + 2]);
        float c[9];
        c[0] = vn[3 * v0]; c[1] = vn[3 * v0 + 1]; c[2] = vn[3 * v0 + 2];
        c[3] = vn[3 * v1]; c[4] = vn[3 * v1 + 1]; c[5] = vn[3 * v1 + 2];
        c[6] = vn[3 * v2]; c[7] = vn[3 * v2 + 1]; c[8] = vn[3 * v2 + 2];

        unsigned long long lo = q14(c[0]) | (q14(c[1]) << 14) | (q14(c[2]) << 28)
                              | (q14(c[3]) << 42) | ((q14(c[4]) & 0xFFull) << 56);
        unsigned long long hi = (q14(c[4]) >> 8) | (q14(c[5]) << 6) | (q14(c[6]) << 20)
                              | (q14(c[7]) << 34)
                              | ((unsigned long long)((unsigned)__float2int_rn(c[8] * Q14_SCALE) & 0xFFFFu) << 48);

        uint4 r;
        r.x = (unsigned)lo;
        r.y = (unsigned)(lo >> 32);
        r.z = (unsigned)hi;
        r.w = (unsigned)(hi >> 32);
        g_facen[f] = r;
    }
#if __CUDA_ARCH__ >= 900
    cudaTriggerProgrammaticLaunchCompletion();
#endif
}

__device__ __forceinline__ int sext14(unsigned v) {
    return ((int)(v << 18)) >> 18;
}

// Decode + blend for one half-pixel (4 fragments); shared by both phases.
__device__ __forceinline__ void blend_half(
    const int* f, const float* z, const float* d, const float* b,
    const uint4* rr, float4* out, int p, int h) {

    float zinv[4];
    float zl = EPSV;
#pragma unroll
    for (int k = 0; k < 4; k++) {
        bool m = f[k] >= 0;
        zinv[k] = m ? (ZFARV - z[k]) * (1.0f / (ZFARV - ZNEARV)) : 0.0f;
        zl = fmaxf(zl, zinv[k]);
    }
    float zmax = fmaxf(zl, __shfl_xor_sync(0xffffffffu, zl, 1));

    float ax = 0.f, ay = 0.f, az = 0.f, wsum = 0.f, om = 1.0f;

#pragma unroll
    for (int k = 0; k < 4; k++) {
        bool m = f[k] >= 0;
        uint4 r = rr[k];

        float prob = m ? __fdividef(1.0f, 1.0f + __expf(d[k] * SIGMA_INV)) : 0.0f;
        om *= (1.0f - prob);
        float w = prob * __expf((zinv[k] - zmax) * GAMMA_INV);
        wsum += w;

        float s = w * Q14_INV;
        float w0 = b[3 * k + 0] * s;
        float w1 = b[3 * k + 1] * s;
        float w2 = b[3 * k + 2] * s;

        int c0 = sext14(r.x);
        int c1 = ((int)(r.x << 4)) >> 18;
        int c2 = sext14(__funnelshift_r(r.x, r.y, 28));
        int c3 = ((int)(r.y << 8)) >> 18;
        int c4 = sext14(__funnelshift_r(r.y, r.z, 24));
        int c5 = ((int)(r.z << 12)) >> 18;
        int c6 = sext14(__funnelshift_r(r.z, r.w, 20));
        int c7 = ((int)(r.w << 16)) >> 18;
        int c8 = ((int)r.w) >> 16;

        ax += w0 * (float)c0 + w1 * (float)c3 + w2 * (float)c6;
        ay += w0 * (float)c1 + w1 * (float)c4 + w2 * (float)c7;
        az += w0 * (float)c2 + w1 * (float)c5 + w2 * (float)c8;
    }

    ax   += __shfl_xor_sync(0xffffffffu, ax,   1);
    ay   += __shfl_xor_sync(0xffffffffu, ay,   1);
    az   += __shfl_xor_sync(0xffffffffu, az,   1);
    wsum += __shfl_xor_sync(0xffffffffu, wsum, 1);
    om   *= __shfl_xor_sync(0xffffffffu, om,   1);

    float delta = __expf((EPSV - zmax) * GAMMA_INV);
    wsum += delta;
    float inv = __fdividef(1.0f, wsum);

    if (h == 0) {
        float4 o = make_float4((ax + delta) * inv,
                               (ay + delta) * inv,
                               (az + delta) * inv,
                               1.0f - om);
        __stcs(&out[p], o);
    }
}

// Each thread processes TWO half-pixels (hp and hp+S). All ~20 loads for both
// are issued before either compute phase: phase-B gathers land during phase-A
// compute, doubling per-thread MLP and interleaving load/compute duty cycles.
__global__ void __launch_bounds__(256, 2)
shade_blend_kernel(const float4* __restrict__ bary,   // 6 float4 per pixel
                   const float4* __restrict__ zbuf,   // 2 float4 per pixel
                   const float4* __restrict__ dists,  // 2 float4 per pixel
                   const int4*   __restrict__ p2f,    // 2 int4 per pixel
                   float4*       __restrict__ out,    // 1 float4 per pixel
                   int npix, int S) {                  // S = npix (threads)
#if __CUDA_ARCH__ >= 900
    cudaGridDependencySynchronize();
#endif

    int i = blockIdx.x * blockDim.x + threadIdx.x;
    if (i >= S) return;

    const int hpA = i,      pA = hpA >> 1, hA = hpA & 1;
    const int hpB = i + S,  pB = hpB >> 1, hB = hpB & 1;

    // ---- issue ALL loads for both half-pixels ----
    int fA[4]; *reinterpret_cast<int4*>(fA) = __ldcs(&p2f[pA * 2 + hA]);
    int fB[4]; *reinterpret_cast<int4*>(fB) = __ldcs(&p2f[pB * 2 + hB]);

    uint4 rA[4], rB[4];
#pragma unroll
    for (int k = 0; k < 4; k++) rA[k] = __ldg(&g_facen[fA[k] >= 0 ? fA[k] : 0]);
#pragma unroll
    for (int k = 0; k < 4; k++) rB[k] = __ldg(&g_facen[fB[k] >= 0 ? fB[k] : 0]);

    float zA[4]; *reinterpret_cast<float4*>(zA) = __ldcs(&zbuf[pA * 2 + hA]);
    float dA[4]; *reinterpret_cast<float4*>(dA) = __ldcs(&dists[pA * 2 + hA]);
    float zB[4]; *reinterpret_cast<float4*>(zB) = __ldcs(&zbuf[pB * 2 + hB]);
    float dB[4]; *reinterpret_cast<float4*>(dB) = __ldcs(&dists[pB * 2 + hB]);

    float bA[12], bB[12];
    {
        float4* v = reinterpret_cast<float4*>(bA);
#pragma unroll
        for (int j = 0; j < 3; j++) v[j] = __ldcs(&bary[pA * 6 + hA * 3 + j]);
    }
    {
        float4* v = reinterpret_cast<float4*>(bB);
#pragma unroll
        for (int j = 0; j < 3; j++) v[j] = __ldcs(&bary[pB * 6 + hB * 3 + j]);
    }

    // ---- compute phase A, then B (B's loads already long in flight) ----
    blend_half(fA, zA, dA, bA, rA, out, pA, hA);
    blend_half(fB, zB, dB, bB, rB, out, pB, hB);
}

extern "C" void kernel_launch(void* const* d_in, const int* in_sizes, int n_in,
                              void* d_out, int out_size) {
    // metadata order: bary_coords, zbuf, dists, verts_normals, pix_to_face, faces
    const float* bary  = (const float*)d_in[0];
    const float* zbuf  = (const float*)d_in[1];
    const float* dists = (const float*)d_in[2];
    const float* vn    = (const float*)d_in[3];
    const int*   p2f   = (const int*)d_in[4];
    const int*   faces = (const int*)d_in[5];

    const int F = in_sizes[5] / 3;
    const int npix = in_sizes[1] / 8;
    const int S = npix;   // nhalf/2 threads; each does hp=i and hp=i+S

    {
        int threads = 256;
        int blocks = (F + threads - 1) / threads;
        gather_face_normals_kernel<<<blocks, threads>>>(faces, vn, F);
    }
    {
        int threads = 256;
        int blocks = (S + threads - 1) / threads;

        cudaLaunchConfig_t cfg = {};
        cfg.gridDim  = dim3((unsigned)blocks, 1, 1);
        cfg.blockDim = dim3((unsigned)threads, 1, 1);
        cfg.dynamicSmemBytes = 0;
        cfg.stream = 0;
        cudaLaunchAttribute attrs[1];
        attrs[0].id = cudaLaunchAttributeProgrammaticStreamSerialization;
        attrs[0].val.programmaticStreamSerializationAllowed = 1;
        cfg.attrs = attrs;
        cfg.numAttrs = 1;

        cudaLaunchKernelEx(&cfg, shade_blend_kernel,
                           (const float4*)bary, (const float4*)zbuf,
                           (const float4*)dists, (const int4*)p2f,
                           (float4*)d_out, npix, S);
    }
}

// round 16
// speedup vs baseline: 1.2693x; 1.2693x over previous
#include <cuda_runtime.h>
#include <cstdint>

// Problem constants (from reference)
#define SIGMA_INV 1.0e4f   // 1/SIGMA
#define GAMMA_INV 1.0e4f   // 1/GAMMA
#define ZFARV 100.0f
#define ZNEARV 1.0f
#define EPSV 1e-10f
#define MAX_F 100000
#define Q14_SCALE 8191.0f
#define Q14_INV   (1.0f / 8191.0f)

// Packed per-face record, 16 bytes: components c0..c7 as 14-bit snorm at bit
// 14*i, c8 as 16-bit slot at bit 112 (quantized with scale 8191).
// Component order: n0x n0y n0z n1x n1y n1z n2x n2y n2z  ->  c0..c8
__device__ uint4 g_facen[MAX_F];

__device__ __forceinline__ unsigned long long q14(float a) {
    int ia = __float2int_rn(a * Q14_SCALE);
    return (unsigned long long)((unsigned)ia & 0x3FFFu);
}

__global__ void gather_face_normals_kernel(const int* __restrict__ faces,
                                           const float* __restrict__ vn,
                                           int F) {
#if __CUDA_ARCH__ >= 900
    // Fire the PDL trigger FIRST: the dependent shade grid may begin
    // launching (and issuing its table-independent stream loads) while this
    // kernel is still building the table. Correctness is enforced by the
    // shade kernel's cudaGridDependencySynchronize(), which waits for this
    // grid's full completion (all stores visible).
    cudaTriggerProgrammaticLaunchCompletion();
#endif
    int f = blockIdx.x * blockDim.x + threadIdx.x;
    if (f < F) {
        int v0 = __ldg(&faces[3 * f + 0]);
        int v1 = __ldg(&faces[3 * f + 1]);
        int v2 = __ldg(&faces[3 * f + 2]);
        float c[9];
        c[0] = vn[3 * v0]; c[1] = vn[3 * v0 + 1]; c[2] = vn[3 * v0 + 2];
        c[3] = vn[3 * v1]; c[4] = vn[3 * v1 + 1]; c[5] = vn[3 * v1 + 2];
        c[6] = vn[3 * v2]; c[7] = vn[3 * v2 + 1]; c[8] = vn[3 * v2 + 2];

        unsigned long long lo = q14(c[0]) | (q14(c[1]) << 14) | (q14(c[2]) << 28)
                              | (q14(c[3]) << 42) | ((q14(c[4]) & 0xFFull) << 56);
        unsigned long long hi = (q14(c[4]) >> 8) | (q14(c[5]) << 6) | (q14(c[6]) << 20)
                              | (q14(c[7]) << 34)
                              | ((unsigned long long)((unsigned)__float2int_rn(c[8] * Q14_SCALE) & 0xFFFFu) << 48);

        uint4 r;
        r.x = (unsigned)lo;
        r.y = (unsigned)(lo >> 32);
        r.z = (unsigned)hi;
        r.w = (unsigned)(hi >> 32);
        g_facen[f] = r;
    }
}

__device__ __forceinline__ int sext14(unsigned v) {
    return ((int)(v << 18)) >> 18;
}

// 2 threads per pixel: thread half h in {0,1} handles fragments 4h..4h+3.
// Stream loads (p2f, z, d, bary) issue first; the grid-dependency sync on the
// prep kernel sits immediately before the face-table gathers, so the stream
// preamble overlaps the prep kernel's execution (PDL).
__global__ void __launch_bounds__(256, 4)
shade_blend_kernel(const float4* __restrict__ bary,   // 6 float4 per pixel
                   const float4* __restrict__ zbuf,   // 2 float4 per pixel
                   const float4* __restrict__ dists,  // 2 float4 per pixel
                   const int4*   __restrict__ p2f,    // 2 int4 per pixel
                   float4*       __restrict__ out,    // 1 float4 per pixel
                   int npix) {
    int tg = blockIdx.x * blockDim.x + threadIdx.x;
    int p = tg >> 1;
    if (p >= npix) {
#if __CUDA_ARCH__ >= 900
        cudaGridDependencySynchronize();
#endif
        return;
    }
    int h = tg & 1;

    // ---- stream loads first (do not depend on the prep kernel) ----
    int f[4]; *reinterpret_cast<int4*>(f) = __ldcs(&p2f[p * 2 + h]);

    float z[4]; *reinterpret_cast<float4*>(z) = __ldcs(&zbuf[p * 2 + h]);
    float d[4]; *reinterpret_cast<float4*>(d) = __ldcs(&dists[p * 2 + h]);

    float b[12];
    float4* bv = reinterpret_cast<float4*>(b);
#pragma unroll
    for (int i = 0; i < 3; i++) bv[i] = __ldcs(&bary[p * 6 + h * 3 + i]);

#if __CUDA_ARCH__ >= 900
    // Wait for the prep kernel's face table before gathering from it.
    cudaGridDependencySynchronize();
#endif

    // ---- face-table gathers: 4 independent 16B loads in flight ----
    uint4 r0 = __ldg(&g_facen[f[0] >= 0 ? f[0] : 0]);
    uint4 r1 = __ldg(&g_facen[f[1] >= 0 ? f[1] : 0]);
    uint4 r2 = __ldg(&g_facen[f[2] >= 0 ? f[2] : 0]);
    uint4 r3 = __ldg(&g_facen[f[3] >= 0 ? f[3] : 0]);

    // ---- compute ----
    float zinv[4];
    float zl = EPSV;
#pragma unroll
    for (int k = 0; k < 4; k++) {
        bool m = f[k] >= 0;
        zinv[k] = m ? (ZFARV - z[k]) * (1.0f / (ZFARV - ZNEARV)) : 0.0f;
        zl = fmaxf(zl, zinv[k]);
    }
    // full-pixel max across the thread pair
    float zmax = fmaxf(zl, __shfl_xor_sync(0xffffffffu, zl, 1));

    float ax = 0.f, ay = 0.f, az = 0.f, wsum = 0.f, om = 1.0f;

    const uint4 rr[4] = {r0, r1, r2, r3};
#pragma unroll
    for (int k = 0; k < 4; k++) {
        bool m = f[k] >= 0;
        uint4 r = rr[k];

        // sigmoid(-d/sigma) = 1/(1+exp(d/sigma)); masked prob -> w = 0 kills
        // any garbage color contribution.
        float prob = m ? __fdividef(1.0f, 1.0f + __expf(d[k] * SIGMA_INV)) : 0.0f;
        om *= (1.0f - prob);
        float w = prob * __expf((zinv[k] - zmax) * GAMMA_INV);
        wsum += w;

        float s = w * Q14_INV;           // fold weight + dequant scale
        float w0 = b[3 * k + 0] * s;
        float w1 = b[3 * k + 1] * s;
        float w2 = b[3 * k + 2] * s;

        int c0 = sext14(r.x);
        int c1 = ((int)(r.x << 4)) >> 18;
        int c2 = sext14(__funnelshift_r(r.x, r.y, 28));
        int c3 = ((int)(r.y << 8)) >> 18;
        int c4 = sext14(__funnelshift_r(r.y, r.z, 24));
        int c5 = ((int)(r.z << 12)) >> 18;
        int c6 = sext14(__funnelshift_r(r.z, r.w, 20));
        int c7 = ((int)(r.w << 16)) >> 18;
        int c8 = ((int)r.w) >> 16;

        ax += w0 * (float)c0 + w1 * (float)c3 + w2 * (float)c6;
        ay += w0 * (float)c1 + w1 * (float)c4 + w2 * (float)c7;
        az += w0 * (float)c2 + w1 * (float)c5 + w2 * (float)c8;
    }

    // combine the two half-pixel partials
    ax   += __shfl_xor_sync(0xffffffffu, ax,   1);
    ay   += __shfl_xor_sync(0xffffffffu, ay,   1);
    az   += __shfl_xor_sync(0xffffffffu, az,   1);
    wsum += __shfl_xor_sync(0xffffffffu, wsum, 1);
    om   *= __shfl_xor_sync(0xffffffffu, om,   1);

    float delta = __expf((EPSV - zmax) * GAMMA_INV);
    wsum += delta;
    float inv = __fdividef(1.0f, wsum);

    if (h == 0) {
        float4 o = make_float4((ax + delta) * inv,
                               (ay + delta) * inv,
                               (az + delta) * inv,
                               1.0f - om);
        __stcs(&out[p], o);
    }
}

extern "C" void kernel_launch(void* const* d_in, const int* in_sizes, int n_in,
                              void* d_out, int out_size) {
    // metadata order: bary_coords, zbuf, dists, verts_normals, pix_to_face, faces
    const float* bary  = (const float*)d_in[0];
    const float* zbuf  = (const float*)d_in[1];
    const float* dists = (const float*)d_in[2];
    const float* vn    = (const float*)d_in[3];
    const int*   p2f   = (const int*)d_in[4];
    const int*   faces = (const int*)d_in[5];

    const int F = in_sizes[5] / 3;
    const int npix = in_sizes[1] / 8;

    {
        int threads = 256;
        int blocks = (F + threads - 1) / threads;
        gather_face_normals_kernel<<<blocks, threads>>>(faces, vn, F);
    }
    {
        int threads = 256;
        long long nthreads = (long long)npix * 2;
        int blocks = (int)((nthreads + threads - 1) / threads);

        // Launch shade with Programmatic Stream Serialization so it overlaps
        // the prep kernel; the device-side grid sync orders the table reads.
        cudaLaunchConfig_t cfg = {};
        cfg.gridDim  = dim3((unsigned)blocks, 1, 1);
        cfg.blockDim = dim3((unsigned)threads, 1, 1);
        cfg.dynamicSmemBytes = 0;
        cfg.stream = 0;
        cudaLaunchAttribute attrs[1];
        attrs[0].id = cudaLaunchAttributeProgrammaticStreamSerialization;
        attrs[0].val.programmaticStreamSerializationAllowed = 1;
        cfg.attrs = attrs;
        cfg.numAttrs = 1;

        cudaLaunchKernelEx(&cfg, shade_blend_kernel,
                           (const float4*)bary, (const float4*)zbuf,
                           (const float4*)dists, (const int4*)p2f,
                           (float4*)d_out, npix);
    }
}